// round 6
// baseline (speedup 1.0000x reference)
#include <cuda_runtime.h>
#include <cuda_bf16.h>
#include <cstdint>

// Problem constants
#define T_ 2048
#define B_ 64
#define D_ 256
#define H_ 256
#define L_ 2
#define M_ (T_ * B_)       // 131072 GEMM rows per layer

// W image: per (l, ntile 0..3): 8 blocks (0-3 = W_hi k-chunks, 4-7 = W_lo),
// each block 256 n-rows x 64 k bf16 = 32KB, rows 128B, XOR-swizzled.
__device__ __align__(16) unsigned char g_W[(size_t)L_ * 4 * 8 * 32768]; // 2 MB
// A image: per m-tile (128 rows): [hi kb0..3 | lo kb0..3], 8 x 16KB = 128KB.
// Block: 128 m-rows x 64 k bf16, row 128B, unit swz = ((j ^ (mloc&7))<<4).
__device__ __align__(16) unsigned char g_A[(size_t)(M_ / 128) * 131072]; // 134 MB
__device__ __align__(16) float4 g_bias4[(size_t)L_ * B_ * H_];          // [l][b][h].(f,i,g,o)

// ---------------------------------------------------------------------------
// helpers
// ---------------------------------------------------------------------------
__device__ __forceinline__ uint32_t smem_u32(const void* p)
{
    uint32_t a;
    asm("{ .reg .u64 t; cvta.to.shared.u64 t, %1; cvt.u32.u64 %0, t; }" : "=r"(a) : "l"(p));
    return a;
}
__device__ __forceinline__ unsigned short bf16_bits(__nv_bfloat16 v)
{
    return *reinterpret_cast<unsigned short*>(&v);
}
__device__ __forceinline__ float sigmoidf_(float x)
{
    return __fdividef(1.0f, 1.0f + __expf(-x));
}
__device__ __forceinline__ float tanhf_(float x)
{
    return 1.0f - __fdividef(2.0f, 1.0f + __expf(2.0f * x));
}
__device__ __forceinline__ uint32_t pack_bf16x2(float a, float b)
{
    __nv_bfloat16 e0 = __float2bfloat16(a);
    __nv_bfloat16 e1 = __float2bfloat16(b);
    return (uint32_t)bf16_bits(e0) | ((uint32_t)bf16_bits(e1) << 16);
}

#define CP16(s, g) asm volatile("cp.async.cg.shared.global [%0], [%1], 16;" :: "r"(s), "l"(g))
#define CP_COMMIT() asm volatile("cp.async.commit_group;" ::: "memory")
#define CP_WAIT1() asm volatile("cp.async.wait_group 1;" ::: "memory")
#define CP_WAIT0() asm volatile("cp.async.wait_group 0;" ::: "memory")

#define LDSM4(r, addr) asm volatile( \
    "ldmatrix.sync.aligned.m8n8.x4.shared.b16 {%0,%1,%2,%3}, [%4];" \
    : "=r"((r)[0]), "=r"((r)[1]), "=r"((r)[2]), "=r"((r)[3]) : "r"(addr))

#define MMA(d, a, b0, b1) asm volatile( \
    "mma.sync.aligned.m16n8k16.row.col.f32.bf16.bf16.f32 " \
    "{%0,%1,%2,%3},{%4,%5,%6,%7},{%8,%9},{%0,%1,%2,%3};" \
    : "+f"((d)[0]), "+f"((d)[1]), "+f"((d)[2]), "+f"((d)[3]) \
    : "r"((a)[0]), "r"((a)[1]), "r"((a)[2]), "r"((a)[3]), "r"(b0), "r"(b1))

// ---------------------------------------------------------------------------
// Kernel 1: W -> bf16 hi/lo image, swizzled blocks (n = h*4+g gate interleave)
// ---------------------------------------------------------------------------
__global__ void __launch_bounds__(256) wprep_kernel(const float* __restrict__ W)
{
    int idx = blockIdx.x * 256 + threadIdx.x;     // 131072 total
    int nloc = idx & 255;
    int j = (idx >> 8) & 7;
    int rest = idx >> 11;                          // ((l*4+nt)*8 + blk), 0..63
    int blk = rest & 7;
    int nt = (rest >> 3) & 3;
    int l = rest >> 5;
    int hl = blk >> 2, kb = blk & 3;
    int n = nt * 256 + nloc, g = n & 3, h = n >> 2;
    int k0 = kb * 64 + j * 8;

    const float* wp = W + ((size_t)(l * 4 + g) * 512 + k0) * 256 + h;
    unsigned short v[8];
#pragma unroll
    for (int i = 0; i < 8; i++) {
        float w = wp[(size_t)i * 256];
        __nv_bfloat16 e = __float2bfloat16(w);
        if (hl)
            e = __float2bfloat16(w - __bfloat162float(e));
        v[i] = bf16_bits(e);
    }
    uint4 out;
    out.x = (uint32_t)v[0] | ((uint32_t)v[1] << 16);
    out.y = (uint32_t)v[2] | ((uint32_t)v[3] << 16);
    out.z = (uint32_t)v[4] | ((uint32_t)v[5] << 16);
    out.w = (uint32_t)v[6] | ((uint32_t)v[7] << 16);
    unsigned off = (unsigned)nloc * 128 + (((unsigned)j ^ ((unsigned)nloc & 7)) << 4);
    *(uint4*)(g_W + (size_t)rest * 32768 + off) = out;
}

// ---------------------------------------------------------------------------
// Kernel 2: A(fp32) -> bf16 hi/lo swizzled image g_A (layer 0 inputs only).
// ---------------------------------------------------------------------------
__global__ void __launch_bounds__(256) aprep_kernel(const float* __restrict__ A, int t_stride)
{
    int idx = blockIdx.x * 256 + threadIdx.x;      // 4,194,304
    int k8 = idx & 31;
    int m = idx >> 5;

    const float* gp = A + (size_t)(m >> 6) * t_stride + (size_t)(m & 63) * 256 + k8 * 8;
    float4 va = *(const float4*)gp;
    float4 vb = *(const float4*)(gp + 4);
    float v[8] = { va.x, va.y, va.z, va.w, vb.x, vb.y, vb.z, vb.w };
    uint32_t hi[4], lo[4];
#pragma unroll
    for (int p = 0; p < 4; p++) {
        float h0f = __bfloat162float(__float2bfloat16(v[2 * p]));
        float h1f = __bfloat162float(__float2bfloat16(v[2 * p + 1]));
        hi[p] = pack_bf16x2(v[2 * p], v[2 * p + 1]);
        lo[p] = pack_bf16x2(v[2 * p] - h0f, v[2 * p + 1] - h1f);
    }
    int mt = m >> 7, mloc = m & 127, kb = k8 >> 3, j = k8 & 7;
    size_t base = (size_t)mt * 131072 + (size_t)kb * 16384 + (size_t)mloc * 128 +
                  (((unsigned)j ^ ((unsigned)mloc & 7)) << 4);
    *(uint4*)(g_A + base) = make_uint4(hi[0], hi[1], hi[2], hi[3]);
    *(uint4*)(g_A + base + 65536) = make_uint4(lo[0], lo[1], lo[2], lo[3]);
}

// ---------------------------------------------------------------------------
// Kernel 3: effective bias (exact fp32): b[l,g,h] + sum_j h0[l,b,j]*W[l,g,D+j,h]
// ---------------------------------------------------------------------------
__global__ void __launch_bounds__(256) bias_kernel(const float* __restrict__ h0,
                                                   const float* __restrict__ W,
                                                   const float* __restrict__ bb)
{
    int idx = blockIdx.x * 256 + threadIdx.x;      // 131072
    int g = idx & 3;
    int h = (idx >> 2) & 255;
    int b = (idx >> 10) & 63;
    int l = idx >> 16;

    const float* h0p = h0 + (l * B_ + b) * H_;
    const float* wp  = W + ((size_t)(l * 4 + g) * 512 + 256) * 256 + h;
    float acc = bb[(l * 4 + g) * H_ + h];
#pragma unroll 8
    for (int j = 0; j < H_; j++)
        acc = fmaf(h0p[j], wp[(size_t)j * 256], acc);
    ((float*)g_bias4)[idx] = acc;
}

// ---------------------------------------------------------------------------
// Kernel 4: HMMA GEMM (3-term bf16 split) + fused LSTM epilogue.
//   CTA: 128m x 256n, 512 threads = 16 warps (4m x 4n), warp tile 32x64.
//   A+B streamed via cp.async; chunk = [A 16KB | B 32KB], 3 bufs, 1 sync/chunk.
//   Chunk c: s=c>>2 (term), kb=c&3. Terms: [Ah*Wh][Al*Wh][Ah*Wl].
//   Epilogue: per thread 8 consecutive h of one row; layer 0 also emits the
//   bf16 hi/lo A-image for layer 1 directly (write_a != 0).
// ---------------------------------------------------------------------------
#define CHUNK_BYTES 49152u
#define SMEM_SZ 147456

__global__ void __launch_bounds__(512, 1)
gemm_kernel(const float* __restrict__ c0, int l,
            float* __restrict__ hn, float* __restrict__ cn,
            float* __restrict__ x_out, int write_a)
{
    extern __shared__ __align__(1024) unsigned char smem[];
    const int tid = threadIdx.x;
    const int bx = blockIdx.x;
    const int by = blockIdx.y;
    const int m0 = by * 128;
    const uint32_t su = smem_u32(smem);
    const int lane = tid & 31, wid = tid >> 5;
    const int wm = wid >> 2, wn = wid & 3;

    const unsigned char* gWb = g_W + (size_t)(l * 4 + bx) * 262144;
    const unsigned char* gAb = g_A + (size_t)by * 131072;

    // chunk copy: 512 threads, A (2 units) + B (4 units) per thread
#define ISSUE_CHUNK(c, buf)                                                     \
    do {                                                                        \
        int s_ = (c) >> 2, kb_ = (c) & 3;                                       \
        const unsigned char* sa = gAb + (s_ == 1 ? 65536 : 0) + kb_ * 16384 + tid * 16; \
        const unsigned char* sb = gWb + (size_t)(s_ == 2 ? 4 + kb_ : kb_) * 32768 + tid * 16; \
        uint32_t da = su + (buf) * CHUNK_BYTES + tid * 16;                      \
        uint32_t db = da + 16384u;                                              \
        CP16(da, sa); CP16(da + 8192, sa + 8192);                               \
        CP16(db, sb); CP16(db + 8192, sb + 8192);                               \
        CP16(db + 16384, sb + 16384); CP16(db + 24576, sb + 24576);             \
        CP_COMMIT();                                                            \
    } while (0)

    // prologue: prefill chunks 0, 1
    ISSUE_CHUNK(0, 0);
    ISSUE_CHUNK(1, 1);

    // per-lane ldmatrix offsets
    uint32_t aoff[2], aswz[2], boff[4], bswz[4];
    const uint32_t ua = (uint32_t)(lane >> 4);
    const uint32_t ub = (uint32_t)((lane >> 3) & 1);
#pragma unroll
    for (int tm = 0; tm < 2; tm++) {
        uint32_t row = (uint32_t)(wm * 32 + tm * 16 + (lane & 15));
        aoff[tm] = row * 128u;
        aswz[tm] = row & 7u;
    }
#pragma unroll
    for (int tn = 0; tn < 4; tn++) {
        uint32_t row = (uint32_t)(wn * 64 + tn * 16 + (lane & 7) + ((lane >> 4) << 3));
        boff[tn] = row * 128u;
        bswz[tn] = row & 7u;
    }

    float acc[2][8][4];
#pragma unroll
    for (int i = 0; i < 2; i++)
#pragma unroll
        for (int j = 0; j < 8; j++)
#pragma unroll
            for (int q = 0; q < 4; q++) acc[i][j][q] = 0.0f;

    // mainloop: 12 chunks (K' = 768), single sync per chunk
#pragma unroll 1
    for (int c = 0; c < 12; c++) {
        const int buf = c - (c / 3) * 3;          // c % 3
        if (c == 11) { CP_WAIT0(); } else { CP_WAIT1(); }
        __syncthreads();

        if (c + 2 < 12) {
            int cn2 = c + 2;
            int bufn = cn2 - (cn2 / 3) * 3;
            ISSUE_CHUNK(cn2, bufn);
        }

        const uint32_t abase = su + (uint32_t)buf * CHUNK_BYTES;
        const uint32_t bbase = abase + 16384u;

#pragma unroll
        for (int ks = 0; ks < 4; ks++) {
            uint32_t a[2][4], bbf[4][4];
#pragma unroll
            for (int tm = 0; tm < 2; tm++)
                LDSM4(a[tm], abase + aoff[tm] +
                              ((((uint32_t)(ks * 2) + ua) ^ aswz[tm]) << 4));
#pragma unroll
            for (int tn = 0; tn < 4; tn++)
                LDSM4(bbf[tn], bbase + boff[tn] +
                               ((((uint32_t)(ks * 2) + ub) ^ bswz[tn]) << 4));
#pragma unroll
            for (int tm = 0; tm < 2; tm++)
#pragma unroll
                for (int tn = 0; tn < 4; tn++) {
                    MMA(acc[tm][tn * 2 + 0], a[tm], bbf[tn][0], bbf[tn][1]);
                    MMA(acc[tm][tn * 2 + 1], a[tm], bbf[tn][2], bbf[tn][3]);
                }
        }
    }
    __syncthreads();

    // stage accumulators to smem (row pad 268 floats)
    {
        float* stage = (float*)smem;
        const int r0 = lane >> 2, cp2 = (lane & 3) * 2;
#pragma unroll
        for (int tm = 0; tm < 2; tm++) {
            int mr = wm * 32 + tm * 16 + r0;
#pragma unroll
            for (int j = 0; j < 8; j++) {
                int nc = wn * 64 + j * 8 + cp2;
                stage[(size_t)mr * 268 + nc]           = acc[tm][j][0];
                stage[(size_t)mr * 268 + nc + 1]       = acc[tm][j][1];
                stage[(size_t)(mr + 8) * 268 + nc]     = acc[tm][j][2];
                stage[(size_t)(mr + 8) * 268 + nc + 1] = acc[tm][j][3];
            }
        }
    }
    __syncthreads();

    // fused LSTM epilogue: each item = (row mloc, 8 consecutive h)
    {
        const float* stage = (const float*)smem;
#pragma unroll 1
        for (int u = 0; u < 2; u++) {
            int item = u * 512 + tid;             // 1024 items
            int hu = item & 7, mloc = item >> 3;
            int m = m0 + mloc;
            int t = m >> 6, b = m & 63;
            int hbase = bx * 64 + hu * 8;

            const float4* bp = g_bias4 + (size_t)(l * B_ + b) * H_ + hbase;
            const float* c0p = c0 + ((size_t)l * B_ + b) * H_ + hbase;
            float hv[8], cc[8];
#pragma unroll
            for (int q = 0; q < 8; q++) {
                float4 pre = *(const float4*)&stage[(size_t)mloc * 268 + (hu * 8 + q) * 4];
                float4 bv = bp[q];
                float f  = sigmoidf_(pre.x + bv.x);
                float ii = sigmoidf_(pre.y + bv.y);
                float gt = tanhf_(pre.z + bv.z);
                float o  = sigmoidf_(pre.w + bv.w);
                cc[q] = fmaf(f, c0p[q], ii * gt);
                hv[q] = o * tanhf_(cc[q]);
            }
            size_t ob = (size_t)t * (L_ * B_ * H_) + (size_t)l * (B_ * H_) +
                        (size_t)b * H_ + hbase;
            *(float4*)&hn[ob]     = make_float4(hv[0], hv[1], hv[2], hv[3]);
            *(float4*)&hn[ob + 4] = make_float4(hv[4], hv[5], hv[6], hv[7]);
            *(float4*)&cn[ob]     = make_float4(cc[0], cc[1], cc[2], cc[3]);
            *(float4*)&cn[ob + 4] = make_float4(cc[4], cc[5], cc[6], cc[7]);

            if (write_a) {
                // emit bf16 hi/lo A-image unit for the next layer
                uint32_t hi[4], lo[4];
#pragma unroll
                for (int p = 0; p < 4; p++) {
                    float h0f = __bfloat162float(__float2bfloat16(hv[2 * p]));
                    float h1f = __bfloat162float(__float2bfloat16(hv[2 * p + 1]));
                    hi[p] = pack_bf16x2(hv[2 * p], hv[2 * p + 1]);
                    lo[p] = pack_bf16x2(hv[2 * p] - h0f, hv[2 * p + 1] - h1f);
                }
                int k8 = hbase >> 3;              // unit index 0..31
                int kb = k8 >> 3, j = k8 & 7;
                size_t base = (size_t)(m >> 7) * 131072 + (size_t)kb * 16384 +
                              (size_t)mloc * 128 +
                              (((unsigned)j ^ ((unsigned)mloc & 7)) << 4);
                *(uint4*)(g_A + base)         = make_uint4(hi[0], hi[1], hi[2], hi[3]);
                *(uint4*)(g_A + base + 65536) = make_uint4(lo[0], lo[1], lo[2], lo[3]);
            } else if (x_out) {
                float* xp = x_out + (size_t)m * H_ + hbase;
                *(float4*)xp       = make_float4(hv[0], hv[1], hv[2], hv[3]);
                *(float4*)(xp + 4) = make_float4(hv[4], hv[5], hv[6], hv[7]);
            }
        }
    }
#undef ISSUE_CHUNK
}

// ---------------------------------------------------------------------------
// Launch. Output layout: [ x (T*B*H) | h_n (T*L*B*H) | c_n (T*L*B*H) ]
// ---------------------------------------------------------------------------
extern "C" void kernel_launch(void* const* d_in, const int* in_sizes, int n_in,
                              void* d_out, int out_size)
{
    const float* inputs = (const float*)d_in[0];   // [T,B,D]
    const float* h0     = (const float*)d_in[1];   // [L,B,H]
    const float* c0     = (const float*)d_in[2];   // [L,B,H]
    const float* W      = (const float*)d_in[3];   // [L,4,D+H,H]
    const float* bb     = (const float*)d_in[4];   // [L,4,H]

    float* out   = (float*)d_out;
    float* x_out = out;
    float* hn    = out + (size_t)T_ * B_ * H_;
    float* cn    = hn + (size_t)T_ * L_ * B_ * H_;

    cudaFuncSetAttribute(gemm_kernel,
                         cudaFuncAttributeMaxDynamicSharedMemorySize, SMEM_SZ);

    wprep_kernel<<<512, 256>>>(W);
    bias_kernel<<<512, 256>>>(h0, W, bb);
    aprep_kernel<<<16384, 256>>>(inputs, B_ * D_);

    dim3 grid(4, M_ / 128);
    // layer 0: epilogue also writes layer-1's A-image (write_a = 1)
    gemm_kernel<<<grid, 512, SMEM_SZ>>>(c0, 0, hn, cn, nullptr, 1);
    // layer 1: writes x
    gemm_kernel<<<grid, 512, SMEM_SZ>>>(c0, 1, hn, cn, x_out, 0);
}

// round 7
// speedup vs baseline: 1.8906x; 1.8906x over previous
#include <cuda_runtime.h>
#include <cuda_bf16.h>
#include <cstdint>

// Problem constants
#define T_ 2048
#define B_ 64
#define D_ 256
#define H_ 256
#define L_ 2
#define M_ (T_ * B_)       // 131072 GEMM rows per layer

// W image: per (l, ntile 0..7): 8 blocks (0-3 = W_hi k-chunks, 4-7 = W_lo),
// each block 128 n-rows x 64 k bf16 = 16KB, rows 128B, XOR-swizzled.
__device__ __align__(16) unsigned char g_W[(size_t)L_ * 8 * 8 * 16384]; // 2 MB
// A image: per m-tile (128 rows): [hi kb0..3 | lo kb0..3], 8 x 16KB = 128KB.
// Block: 128 m-rows x 64 k bf16, row 128B, unit swz = ((j ^ (mloc&7))<<4).
__device__ __align__(16) unsigned char g_A[(size_t)(M_ / 128) * 131072]; // 134 MB
__device__ __align__(16) float4 g_bias4[(size_t)L_ * B_ * H_];          // [l][b][h].(f,i,g,o)

// ---------------------------------------------------------------------------
// helpers
// ---------------------------------------------------------------------------
__device__ __forceinline__ uint32_t smem_u32(const void* p)
{
    uint32_t a;
    asm("{ .reg .u64 t; cvta.to.shared.u64 t, %1; cvt.u32.u64 %0, t; }" : "=r"(a) : "l"(p));
    return a;
}
__device__ __forceinline__ unsigned short bf16_bits(__nv_bfloat16 v)
{
    return *reinterpret_cast<unsigned short*>(&v);
}
__device__ __forceinline__ float sigmoidf_(float x)
{
    return __fdividef(1.0f, 1.0f + __expf(-x));
}
__device__ __forceinline__ float tanhf_(float x)
{
    return 1.0f - __fdividef(2.0f, 1.0f + __expf(2.0f * x));
}
__device__ __forceinline__ uint32_t pack_bf16x2(float a, float b)
{
    __nv_bfloat16 e0 = __float2bfloat16(a);
    __nv_bfloat16 e1 = __float2bfloat16(b);
    return (uint32_t)bf16_bits(e0) | ((uint32_t)bf16_bits(e1) << 16);
}

#define CP16(s, g) asm volatile("cp.async.cg.shared.global [%0], [%1], 16;" :: "r"(s), "l"(g))
#define CP_COMMIT() asm volatile("cp.async.commit_group;" ::: "memory")
#define CP_WAIT1() asm volatile("cp.async.wait_group 1;" ::: "memory")
#define CP_WAIT0() asm volatile("cp.async.wait_group 0;" ::: "memory")

#define LDSM4(r, addr) asm volatile( \
    "ldmatrix.sync.aligned.m8n8.x4.shared.b16 {%0,%1,%2,%3}, [%4];" \
    : "=r"((r)[0]), "=r"((r)[1]), "=r"((r)[2]), "=r"((r)[3]) : "r"(addr))

#define MMA(d, a, b0, b1) asm volatile( \
    "mma.sync.aligned.m16n8k16.row.col.f32.bf16.bf16.f32 " \
    "{%0,%1,%2,%3},{%4,%5,%6,%7},{%8,%9},{%0,%1,%2,%3};" \
    : "+f"((d)[0]), "+f"((d)[1]), "+f"((d)[2]), "+f"((d)[3]) \
    : "r"((a)[0]), "r"((a)[1]), "r"((a)[2]), "r"((a)[3]), "r"(b0), "r"(b1))

// ---------------------------------------------------------------------------
// Kernel 1: W -> bf16 hi/lo image, swizzled 16KB blocks (n = h*4+g interleave)
// ---------------------------------------------------------------------------
__global__ void __launch_bounds__(256) wprep_kernel(const float* __restrict__ W)
{
    int idx = blockIdx.x * 256 + threadIdx.x;     // 131072 total
    int j = idx & 7;
    int nloc = (idx >> 3) & 127;
    int rest = idx >> 10;                          // ((l*8+nt)*8 + blk), 0..127
    int blk = rest & 7;
    int nt = (rest >> 3) & 7;
    int l = rest >> 6;
    int hl = blk >> 2, kb = blk & 3;
    int n = nt * 128 + nloc, g = n & 3, h = n >> 2;
    int k0 = kb * 64 + j * 8;

    const float* wp = W + ((size_t)(l * 4 + g) * 512 + k0) * 256 + h;
    unsigned short v[8];
#pragma unroll
    for (int i = 0; i < 8; i++) {
        float w = wp[(size_t)i * 256];
        __nv_bfloat16 e = __float2bfloat16(w);
        if (hl)
            e = __float2bfloat16(w - __bfloat162float(e));
        v[i] = bf16_bits(e);
    }
    uint4 out;
    out.x = (uint32_t)v[0] | ((uint32_t)v[1] << 16);
    out.y = (uint32_t)v[2] | ((uint32_t)v[3] << 16);
    out.z = (uint32_t)v[4] | ((uint32_t)v[5] << 16);
    out.w = (uint32_t)v[6] | ((uint32_t)v[7] << 16);
    unsigned off = (unsigned)nloc * 128 + (((unsigned)j ^ ((unsigned)nloc & 7)) << 4);
    *(uint4*)(g_W + (size_t)rest * 16384 + off) = out;
}

// ---------------------------------------------------------------------------
// Kernel 2: A(fp32) -> bf16 hi/lo swizzled image g_A (layer 0 inputs only).
// ---------------------------------------------------------------------------
__global__ void __launch_bounds__(256) aprep_kernel(const float* __restrict__ A, int t_stride)
{
    int idx = blockIdx.x * 256 + threadIdx.x;      // 4,194,304
    int k8 = idx & 31;
    int m = idx >> 5;

    const float* gp = A + (size_t)(m >> 6) * t_stride + (size_t)(m & 63) * 256 + k8 * 8;
    float4 va = *(const float4*)gp;
    float4 vb = *(const float4*)(gp + 4);
    float v[8] = { va.x, va.y, va.z, va.w, vb.x, vb.y, vb.z, vb.w };
    uint32_t hi[4], lo[4];
#pragma unroll
    for (int p = 0; p < 4; p++) {
        float h0f = __bfloat162float(__float2bfloat16(v[2 * p]));
        float h1f = __bfloat162float(__float2bfloat16(v[2 * p + 1]));
        hi[p] = pack_bf16x2(v[2 * p], v[2 * p + 1]);
        lo[p] = pack_bf16x2(v[2 * p] - h0f, v[2 * p + 1] - h1f);
    }
    int mt = m >> 7, mloc = m & 127, kb = k8 >> 3, j = k8 & 7;
    size_t base = (size_t)mt * 131072 + (size_t)kb * 16384 + (size_t)mloc * 128 +
                  (((unsigned)j ^ ((unsigned)mloc & 7)) << 4);
    *(uint4*)(g_A + base) = make_uint4(hi[0], hi[1], hi[2], hi[3]);
    *(uint4*)(g_A + base + 65536) = make_uint4(lo[0], lo[1], lo[2], lo[3]);
}

// ---------------------------------------------------------------------------
// Kernel 3: effective bias (exact fp32): b[l,g,h] + sum_j h0[l,b,j]*W[l,g,D+j,h]
// ---------------------------------------------------------------------------
__global__ void __launch_bounds__(256) bias_kernel(const float* __restrict__ h0,
                                                   const float* __restrict__ W,
                                                   const float* __restrict__ bb)
{
    int idx = blockIdx.x * 256 + threadIdx.x;      // 131072
    int g = idx & 3;
    int h = (idx >> 2) & 255;
    int b = (idx >> 10) & 63;
    int l = idx >> 16;

    const float* h0p = h0 + (l * B_ + b) * H_;
    const float* wp  = W + ((size_t)(l * 4 + g) * 512 + 256) * 256 + h;
    float acc = bb[(l * 4 + g) * H_ + h];
#pragma unroll 8
    for (int j = 0; j < H_; j++)
        acc = fmaf(h0p[j], wp[(size_t)j * 256], acc);
    ((float*)g_bias4)[idx] = acc;
}

// ---------------------------------------------------------------------------
// Kernel 4: HMMA GEMM (3-term bf16 split) + fused LSTM epilogue.
//   CTA: 128m x 128n, 256 threads = 8 warps (4m x 2n), warp tile 32x64.
//   A+B streamed via cp.async; chunk = [A 16KB | B 16KB], 3 bufs, 1 sync/chunk.
//   Chunk c: s=c>>2 (term), kb=c&3. Terms: [Ah*Wh][Al*Wh][Ah*Wl].
//   2 CTAs/SM (regs <= 128): cross-CTA overlap of epilogue with mainloop.
//   grid: x = n-tile 0..7 (32 h each), y = m-tile 0..1023.
// ---------------------------------------------------------------------------
#define CHUNK_BYTES 32768u
#define SMEM_SZ 98304

__global__ void __launch_bounds__(256, 2)
gemm_kernel(const float* __restrict__ c0, int l,
            float* __restrict__ hn, float* __restrict__ cn,
            float* __restrict__ x_out, int write_a)
{
    extern __shared__ __align__(1024) unsigned char smem[];
    const int tid = threadIdx.x;
    const int bx = blockIdx.x;
    const int by = blockIdx.y;
    const int m0 = by * 128;
    const uint32_t su = smem_u32(smem);
    const int lane = tid & 31, wid = tid >> 5;
    const int wm = wid >> 1, wn = wid & 1;

    const unsigned char* gWb = g_W + (size_t)(l * 8 + bx) * 131072;
    const unsigned char* gAb = g_A + (size_t)by * 131072;

    // chunk copy: 256 threads, A (4 units) + B (4 units) per thread
#define ISSUE_CHUNK(c, buf)                                                     \
    do {                                                                        \
        int s_ = (c) >> 2, kb_ = (c) & 3;                                       \
        const unsigned char* sa = gAb + (s_ == 1 ? 65536 : 0) + kb_ * 16384 + tid * 16; \
        const unsigned char* sb = gWb + (size_t)(s_ == 2 ? 4 + kb_ : kb_) * 16384 + tid * 16; \
        uint32_t da = su + (buf) * CHUNK_BYTES + tid * 16;                      \
        uint32_t db = da + 16384u;                                              \
        CP16(da, sa); CP16(da + 4096, sa + 4096);                               \
        CP16(da + 8192, sa + 8192); CP16(da + 12288, sa + 12288);               \
        CP16(db, sb); CP16(db + 4096, sb + 4096);                               \
        CP16(db + 8192, sb + 8192); CP16(db + 12288, sb + 12288);               \
        CP_COMMIT();                                                            \
    } while (0)

    // prologue: prefill chunks 0, 1
    ISSUE_CHUNK(0, 0);
    ISSUE_CHUNK(1, 1);

    // per-lane ldmatrix offsets
    uint32_t aoff[2], aswz[2], boff[4], bswz[4];
    const uint32_t ua = (uint32_t)(lane >> 4);
    const uint32_t ub = (uint32_t)((lane >> 3) & 1);
#pragma unroll
    for (int tm = 0; tm < 2; tm++) {
        uint32_t row = (uint32_t)(wm * 32 + tm * 16 + (lane & 15));
        aoff[tm] = row * 128u;
        aswz[tm] = row & 7u;
    }
#pragma unroll
    for (int tn = 0; tn < 4; tn++) {
        uint32_t row = (uint32_t)(wn * 64 + tn * 16 + (lane & 7) + ((lane >> 4) << 3));
        boff[tn] = row * 128u;
        bswz[tn] = row & 7u;
    }

    float acc[2][8][4];
#pragma unroll
    for (int i = 0; i < 2; i++)
#pragma unroll
        for (int j = 0; j < 8; j++)
#pragma unroll
            for (int q = 0; q < 4; q++) acc[i][j][q] = 0.0f;

    // mainloop: 12 chunks (K' = 768), single sync per chunk
#pragma unroll 1
    for (int c = 0; c < 12; c++) {
        const int buf = c - (c / 3) * 3;          // c % 3
        if (c == 11) { CP_WAIT0(); } else { CP_WAIT1(); }
        __syncthreads();

        if (c + 2 < 12) {
            int cn2 = c + 2;
            int bufn = cn2 - (cn2 / 3) * 3;
            ISSUE_CHUNK(cn2, bufn);
        }

        const uint32_t abase = su + (uint32_t)buf * CHUNK_BYTES;
        const uint32_t bbase = abase + 16384u;

#pragma unroll
        for (int ks = 0; ks < 4; ks++) {
            uint32_t a[2][4], bbf[4][4];
#pragma unroll
            for (int tm = 0; tm < 2; tm++)
                LDSM4(a[tm], abase + aoff[tm] +
                              ((((uint32_t)(ks * 2) + ua) ^ aswz[tm]) << 4));
#pragma unroll
            for (int tn = 0; tn < 4; tn++)
                LDSM4(bbf[tn], bbase + boff[tn] +
                               ((((uint32_t)(ks * 2) + ub) ^ bswz[tn]) << 4));
#pragma unroll
            for (int tm = 0; tm < 2; tm++)
#pragma unroll
                for (int tn = 0; tn < 4; tn++) {
                    MMA(acc[tm][tn * 2 + 0], a[tm], bbf[tn][0], bbf[tn][1]);
                    MMA(acc[tm][tn * 2 + 1], a[tm], bbf[tn][2], bbf[tn][3]);
                }
        }
    }
    __syncthreads();

    // stage accumulators to smem (128 rows x 128 cols, row pad 132 floats)
    {
        float* stage = (float*)smem;
        const int r0 = lane >> 2, cp2 = (lane & 3) * 2;
#pragma unroll
        for (int tm = 0; tm < 2; tm++) {
            int mr = wm * 32 + tm * 16 + r0;
#pragma unroll
            for (int j = 0; j < 8; j++) {
                int nc = wn * 64 + j * 8 + cp2;
                stage[(size_t)mr * 132 + nc]           = acc[tm][j][0];
                stage[(size_t)mr * 132 + nc + 1]       = acc[tm][j][1];
                stage[(size_t)(mr + 8) * 132 + nc]     = acc[tm][j][2];
                stage[(size_t)(mr + 8) * 132 + nc + 1] = acc[tm][j][3];
            }
        }
    }
    __syncthreads();

    // fused LSTM epilogue: each item = (row mloc, 8 consecutive h of 32)
    {
        const float* stage = (const float*)smem;
#pragma unroll 1
        for (int u = 0; u < 2; u++) {
            int item = u * 256 + tid;             // 512 items
            int hu = item & 3, mloc = item >> 2;
            int m = m0 + mloc;
            int t = m >> 6, b = m & 63;
            int hbase = bx * 32 + hu * 8;

            const float4* bp = g_bias4 + (size_t)(l * B_ + b) * H_ + hbase;
            const float* c0p = c0 + ((size_t)l * B_ + b) * H_ + hbase;
            float hv[8], cc[8];
#pragma unroll
            for (int q = 0; q < 8; q++) {
                float4 pre = *(const float4*)&stage[(size_t)mloc * 132 + (hu * 8 + q) * 4];
                float4 bv = bp[q];
                float f  = sigmoidf_(pre.x + bv.x);
                float ii = sigmoidf_(pre.y + bv.y);
                float gt = tanhf_(pre.z + bv.z);
                float o  = sigmoidf_(pre.w + bv.w);
                cc[q] = fmaf(f, c0p[q], ii * gt);
                hv[q] = o * tanhf_(cc[q]);
            }
            size_t ob = (size_t)t * (L_ * B_ * H_) + (size_t)l * (B_ * H_) +
                        (size_t)b * H_ + hbase;
            *(float4*)&hn[ob]     = make_float4(hv[0], hv[1], hv[2], hv[3]);
            *(float4*)&hn[ob + 4] = make_float4(hv[4], hv[5], hv[6], hv[7]);
            *(float4*)&cn[ob]     = make_float4(cc[0], cc[1], cc[2], cc[3]);
            *(float4*)&cn[ob + 4] = make_float4(cc[4], cc[5], cc[6], cc[7]);

            if (write_a) {
                // emit bf16 hi/lo A-image unit for the next layer
                uint32_t hi[4], lo[4];
#pragma unroll
                for (int p = 0; p < 4; p++) {
                    float h0f = __bfloat162float(__float2bfloat16(hv[2 * p]));
                    float h1f = __bfloat162float(__float2bfloat16(hv[2 * p + 1]));
                    hi[p] = pack_bf16x2(hv[2 * p], hv[2 * p + 1]);
                    lo[p] = pack_bf16x2(hv[2 * p] - h0f, hv[2 * p + 1] - h1f);
                }
                int k8 = (hbase >> 3);            // unit index 0..31
                int kb = k8 >> 3, j = k8 & 7;
                size_t base = (size_t)(m >> 7) * 131072 + (size_t)kb * 16384 +
                              (size_t)mloc * 128 +
                              (((unsigned)j ^ ((unsigned)mloc & 7)) << 4);
                *(uint4*)(g_A + base)         = make_uint4(hi[0], hi[1], hi[2], hi[3]);
                *(uint4*)(g_A + base + 65536) = make_uint4(lo[0], lo[1], lo[2], lo[3]);
            } else if (x_out) {
                float* xp = x_out + (size_t)m * H_ + hbase;
                *(float4*)xp       = make_float4(hv[0], hv[1], hv[2], hv[3]);
                *(float4*)(xp + 4) = make_float4(hv[4], hv[5], hv[6], hv[7]);
            }
        }
    }
#undef ISSUE_CHUNK
}

// ---------------------------------------------------------------------------
// Launch. Output layout: [ x (T*B*H) | h_n (T*L*B*H) | c_n (T*L*B*H) ]
// ---------------------------------------------------------------------------
extern "C" void kernel_launch(void* const* d_in, const int* in_sizes, int n_in,
                              void* d_out, int out_size)
{
    const float* inputs = (const float*)d_in[0];   // [T,B,D]
    const float* h0     = (const float*)d_in[1];   // [L,B,H]
    const float* c0     = (const float*)d_in[2];   // [L,B,H]
    const float* W      = (const float*)d_in[3];   // [L,4,D+H,H]
    const float* bb     = (const float*)d_in[4];   // [L,4,H]

    float* out   = (float*)d_out;
    float* x_out = out;
    float* hn    = out + (size_t)T_ * B_ * H_;
    float* cn    = hn + (size_t)T_ * L_ * B_ * H_;

    cudaFuncSetAttribute(gemm_kernel,
                         cudaFuncAttributeMaxDynamicSharedMemorySize, SMEM_SZ);

    wprep_kernel<<<512, 256>>>(W);
    bias_kernel<<<512, 256>>>(h0, W, bb);
    aprep_kernel<<<16384, 256>>>(inputs, B_ * D_);

    dim3 grid(8, M_ / 128);
    // layer 0: epilogue also writes layer-1's A-image (write_a = 1)
    gemm_kernel<<<grid, 256, SMEM_SZ>>>(c0, 0, hn, cn, nullptr, 1);
    // layer 1: writes x
    gemm_kernel<<<grid, 256, SMEM_SZ>>>(c0, 1, hn, cn, x_out, 0);
}

// round 8
// speedup vs baseline: 1.9799x; 1.0472x over previous
#include <cuda_runtime.h>
#include <cuda_bf16.h>
#include <cstdint>

// Problem constants
#define T_ 2048
#define B_ 64
#define D_ 256
#define H_ 256
#define L_ 2
#define M_ (T_ * B_)       // 131072 GEMM rows per layer

// W image: per (l, ntile 0..7): 8 blocks (0-3 = W_hi k-chunks, 4-7 = W_lo),
// each block 128 n-rows x 64 k bf16 = 16KB, rows 128B, XOR-swizzled.
__device__ __align__(16) unsigned char g_W[(size_t)L_ * 8 * 8 * 16384]; // 2 MB
// A image: per m-tile (128 rows): [hi kb0..3 | lo kb0..3], 8 x 16KB = 128KB.
// Block: 128 m-rows x 64 k bf16, row 128B, unit swz = ((j ^ (mloc&7))<<4).
__device__ __align__(16) unsigned char g_A[(size_t)(M_ / 128) * 131072]; // 134 MB
__device__ __align__(16) float4 g_bias4[(size_t)L_ * B_ * H_];          // [l][b][h].(f,i,g,o)

// ---------------------------------------------------------------------------
// helpers
// ---------------------------------------------------------------------------
__device__ __forceinline__ uint32_t smem_u32(const void* p)
{
    uint32_t a;
    asm("{ .reg .u64 t; cvta.to.shared.u64 t, %1; cvt.u32.u64 %0, t; }" : "=r"(a) : "l"(p));
    return a;
}
__device__ __forceinline__ unsigned short bf16_bits(__nv_bfloat16 v)
{
    return *reinterpret_cast<unsigned short*>(&v);
}
__device__ __forceinline__ float sigmoidf_(float x)
{
    return __fdividef(1.0f, 1.0f + __expf(-x));
}
__device__ __forceinline__ float tanhf_(float x)
{
    return 1.0f - __fdividef(2.0f, 1.0f + __expf(2.0f * x));
}
__device__ __forceinline__ uint32_t pack_bf16x2(float a, float b)
{
    __nv_bfloat16 e0 = __float2bfloat16(a);
    __nv_bfloat16 e1 = __float2bfloat16(b);
    return (uint32_t)bf16_bits(e0) | ((uint32_t)bf16_bits(e1) << 16);
}

#define CP16(s, g) asm volatile("cp.async.cg.shared.global [%0], [%1], 16;" :: "r"(s), "l"(g))
#define CP_COMMIT() asm volatile("cp.async.commit_group;" ::: "memory")
#define CP_WAIT1() asm volatile("cp.async.wait_group 1;" ::: "memory")
#define CP_WAIT0() asm volatile("cp.async.wait_group 0;" ::: "memory")

#define LDSM4(r, addr) asm volatile( \
    "ldmatrix.sync.aligned.m8n8.x4.shared.b16 {%0,%1,%2,%3}, [%4];" \
    : "=r"((r)[0]), "=r"((r)[1]), "=r"((r)[2]), "=r"((r)[3]) : "r"(addr))

#define MMA(d, a, b0, b1) asm volatile( \
    "mma.sync.aligned.m16n8k16.row.col.f32.bf16.bf16.f32 " \
    "{%0,%1,%2,%3},{%4,%5,%6,%7},{%8,%9},{%0,%1,%2,%3};" \
    : "+f"((d)[0]), "+f"((d)[1]), "+f"((d)[2]), "+f"((d)[3]) \
    : "r"((a)[0]), "r"((a)[1]), "r"((a)[2]), "r"((a)[3]), "r"(b0), "r"(b1))

// ---------------------------------------------------------------------------
// Kernel 1: W -> bf16 hi/lo image, swizzled 16KB blocks (n = h*4+g interleave)
// ---------------------------------------------------------------------------
__global__ void __launch_bounds__(256) wprep_kernel(const float* __restrict__ W)
{
    int idx = blockIdx.x * 256 + threadIdx.x;     // 131072 total
    int j = idx & 7;
    int nloc = (idx >> 3) & 127;
    int rest = idx >> 10;                          // ((l*8+nt)*8 + blk), 0..127
    int blk = rest & 7;
    int nt = (rest >> 3) & 7;
    int l = rest >> 6;
    int hl = blk >> 2, kb = blk & 3;
    int n = nt * 128 + nloc, g = n & 3, h = n >> 2;
    int k0 = kb * 64 + j * 8;

    const float* wp = W + ((size_t)(l * 4 + g) * 512 + k0) * 256 + h;
    unsigned short v[8];
#pragma unroll
    for (int i = 0; i < 8; i++) {
        float w = wp[(size_t)i * 256];
        __nv_bfloat16 e = __float2bfloat16(w);
        if (hl)
            e = __float2bfloat16(w - __bfloat162float(e));
        v[i] = bf16_bits(e);
    }
    uint4 out;
    out.x = (uint32_t)v[0] | ((uint32_t)v[1] << 16);
    out.y = (uint32_t)v[2] | ((uint32_t)v[3] << 16);
    out.z = (uint32_t)v[4] | ((uint32_t)v[5] << 16);
    out.w = (uint32_t)v[6] | ((uint32_t)v[7] << 16);
    unsigned off = (unsigned)nloc * 128 + (((unsigned)j ^ ((unsigned)nloc & 7)) << 4);
    *(uint4*)(g_W + (size_t)rest * 16384 + off) = out;
}

// ---------------------------------------------------------------------------
// Kernel 2: A(fp32) -> bf16 hi/lo swizzled image g_A (layer 0 inputs only).
// ---------------------------------------------------------------------------
__global__ void __launch_bounds__(256) aprep_kernel(const float* __restrict__ A, int t_stride)
{
    int idx = blockIdx.x * 256 + threadIdx.x;      // 4,194,304
    int k8 = idx & 31;
    int m = idx >> 5;

    const float* gp = A + (size_t)(m >> 6) * t_stride + (size_t)(m & 63) * 256 + k8 * 8;
    float4 va = *(const float4*)gp;
    float4 vb = *(const float4*)(gp + 4);
    float v[8] = { va.x, va.y, va.z, va.w, vb.x, vb.y, vb.z, vb.w };
    uint32_t hi[4], lo[4];
#pragma unroll
    for (int p = 0; p < 4; p++) {
        float h0f = __bfloat162float(__float2bfloat16(v[2 * p]));
        float h1f = __bfloat162float(__float2bfloat16(v[2 * p + 1]));
        hi[p] = pack_bf16x2(v[2 * p], v[2 * p + 1]);
        lo[p] = pack_bf16x2(v[2 * p] - h0f, v[2 * p + 1] - h1f);
    }
    int mt = m >> 7, mloc = m & 127, kb = k8 >> 3, j = k8 & 7;
    size_t base = (size_t)mt * 131072 + (size_t)kb * 16384 + (size_t)mloc * 128 +
                  (((unsigned)j ^ ((unsigned)mloc & 7)) << 4);
    *(uint4*)(g_A + base) = make_uint4(hi[0], hi[1], hi[2], hi[3]);
    *(uint4*)(g_A + base + 65536) = make_uint4(lo[0], lo[1], lo[2], lo[3]);
}

// ---------------------------------------------------------------------------
// Kernel 3: effective bias (exact fp32): b[l,g,h] + sum_j h0[l,b,j]*W[l,g,D+j,h]
// ---------------------------------------------------------------------------
__global__ void __launch_bounds__(256) bias_kernel(const float* __restrict__ h0,
                                                   const float* __restrict__ W,
                                                   const float* __restrict__ bb)
{
    int idx = blockIdx.x * 256 + threadIdx.x;      // 131072
    int g = idx & 3;
    int h = (idx >> 2) & 255;
    int b = (idx >> 10) & 63;
    int l = idx >> 16;

    const float* h0p = h0 + (l * B_ + b) * H_;
    const float* wp  = W + ((size_t)(l * 4 + g) * 512 + 256) * 256 + h;
    float acc = bb[(l * 4 + g) * H_ + h];
#pragma unroll 8
    for (int j = 0; j < H_; j++)
        acc = fmaf(h0p[j], wp[(size_t)j * 256], acc);
    ((float*)g_bias4)[idx] = acc;
}

// ---------------------------------------------------------------------------
// Kernel 4: HMMA GEMM (3-term bf16 split) + fused LSTM epilogue.
//   CTA: 128m x 128n, 256 threads = 8 warps (4m x 2n), warp tile 32x64.
//   kb-group schedule: chunk 2kb = (Ah[kb], Wh[kb]), chunk 2kb+1 = (Al[kb], Wl[kb]).
//   Both chunks of a group resident (3-buf ring) -> per ks: 12 LDSM feed 24 MMAs
//   (Ah*Wh, Al*Wh, Ah*Wl with Ah/Wh register reuse). 8 chunks total (no dup A-hi).
//   2 CTAs/SM; grid: x = n-tile 0..7 (32 h each), y = m-tile 0..1023.
// ---------------------------------------------------------------------------
#define CHUNK_BYTES 32768u
#define SMEM_SZ 98304

__global__ void __launch_bounds__(256, 2)
gemm_kernel(const float* __restrict__ c0, int l,
            float* __restrict__ hn, float* __restrict__ cn,
            float* __restrict__ x_out, int write_a)
{
    extern __shared__ __align__(1024) unsigned char smem[];
    const int tid = threadIdx.x;
    const int bx = blockIdx.x;
    const int by = blockIdx.y;
    const int m0 = by * 128;
    const uint32_t su = smem_u32(smem);
    const int lane = tid & 31, wid = tid >> 5;
    const int wm = wid >> 1, wn = wid & 1;

    const unsigned char* gWb = g_W + (size_t)(l * 8 + bx) * 131072;
    const unsigned char* gAb = g_A + (size_t)by * 131072;

    // chunk c (0..7): kb = c>>1; even c -> (Ah[kb], Wh[kb]); odd -> (Al[kb], Wl[kb])
#define ISSUE_CHUNK(c, buf)                                                     \
    do {                                                                        \
        int hl_ = (c) & 1, kb_ = (c) >> 1;                                      \
        const unsigned char* sa = gAb + hl_ * 65536 + kb_ * 16384 + tid * 16;   \
        const unsigned char* sb = gWb + (size_t)(hl_ * 4 + kb_) * 16384 + tid * 16; \
        uint32_t da = su + (buf) * CHUNK_BYTES + tid * 16;                      \
        uint32_t db = da + 16384u;                                              \
        CP16(da, sa); CP16(da + 4096, sa + 4096);                               \
        CP16(da + 8192, sa + 8192); CP16(da + 12288, sa + 12288);               \
        CP16(db, sb); CP16(db + 4096, sb + 4096);                               \
        CP16(db + 8192, sb + 8192); CP16(db + 12288, sb + 12288);               \
        CP_COMMIT();                                                            \
    } while (0)

    // prologue: prefill chunks 0, 1, 2
    ISSUE_CHUNK(0, 0);
    ISSUE_CHUNK(1, 1);
    ISSUE_CHUNK(2, 2);

    // per-lane ldmatrix offsets
    uint32_t aoff[2], aswz[2], boff[4], bswz[4];
    const uint32_t ua = (uint32_t)(lane >> 4);
    const uint32_t ub = (uint32_t)((lane >> 3) & 1);
#pragma unroll
    for (int tm = 0; tm < 2; tm++) {
        uint32_t row = (uint32_t)(wm * 32 + tm * 16 + (lane & 15));
        aoff[tm] = row * 128u;
        aswz[tm] = row & 7u;
    }
#pragma unroll
    for (int tn = 0; tn < 4; tn++) {
        uint32_t row = (uint32_t)(wn * 64 + tn * 16 + (lane & 7) + ((lane >> 4) << 3));
        boff[tn] = row * 128u + 16384u;           // W region offset inside chunk
        bswz[tn] = row & 7u;
    }

    float acc[2][8][4];
#pragma unroll
    for (int i = 0; i < 2; i++)
#pragma unroll
        for (int j = 0; j < 8; j++)
#pragma unroll
            for (int q = 0; q < 4; q++) acc[i][j][q] = 0.0f;

    // mainloop: 4 kb-groups, each = 2 chunks (even: Ah|Wh, odd: Al|Wl)
#pragma unroll 1
    for (int g = 0; g < 4; g++) {
        if (g == 3) { CP_WAIT0(); } else { CP_WAIT1(); }
        __syncthreads();

        const int c0i = 2 * g;
        const uint32_t be = su + (uint32_t)(c0i - (c0i / 3) * 3) * CHUNK_BYTES;       // Ah|Wh
        const uint32_t bo = su + (uint32_t)((c0i + 1) - ((c0i + 1) / 3) * 3) * CHUNK_BYTES; // Al|Wl

#pragma unroll
        for (int ks = 0; ks < 4; ks++) {
            uint32_t ah[2][4], al[2][4], w[4][4];
            const uint32_t ka = (uint32_t)(ks * 2) + ua;
            const uint32_t kbv = (uint32_t)(ks * 2) + ub;

            // term 1: Ah * Wh
#pragma unroll
            for (int tm = 0; tm < 2; tm++)
                LDSM4(ah[tm], be + aoff[tm] + ((ka ^ aswz[tm]) << 4));
#pragma unroll
            for (int tn = 0; tn < 4; tn++)
                LDSM4(w[tn], be + boff[tn] + ((kbv ^ bswz[tn]) << 4));
#pragma unroll
            for (int tm = 0; tm < 2; tm++)
#pragma unroll
                for (int tn = 0; tn < 4; tn++) {
                    MMA(acc[tm][tn * 2 + 0], ah[tm], w[tn][0], w[tn][1]);
                    MMA(acc[tm][tn * 2 + 1], ah[tm], w[tn][2], w[tn][3]);
                }

            // term 2: Al * Wh (Wh still in regs)
#pragma unroll
            for (int tm = 0; tm < 2; tm++)
                LDSM4(al[tm], bo + aoff[tm] + ((ka ^ aswz[tm]) << 4));
#pragma unroll
            for (int tm = 0; tm < 2; tm++)
#pragma unroll
                for (int tn = 0; tn < 4; tn++) {
                    MMA(acc[tm][tn * 2 + 0], al[tm], w[tn][0], w[tn][1]);
                    MMA(acc[tm][tn * 2 + 1], al[tm], w[tn][2], w[tn][3]);
                }

            // term 3: Ah * Wl (Ah still in regs; Wl overwrites Wh regs)
#pragma unroll
            for (int tn = 0; tn < 4; tn++)
                LDSM4(w[tn], bo + boff[tn] + ((kbv ^ bswz[tn]) << 4));
#pragma unroll
            for (int tm = 0; tm < 2; tm++)
#pragma unroll
                for (int tn = 0; tn < 4; tn++) {
                    MMA(acc[tm][tn * 2 + 0], ah[tm], w[tn][0], w[tn][1]);
                    MMA(acc[tm][tn * 2 + 1], ah[tm], w[tn][2], w[tn][3]);
                }
        }
        __syncthreads();

        // refill freed buffers
        if (g == 0) { ISSUE_CHUNK(3, 0); ISSUE_CHUNK(4, 1); }
        else if (g == 1) { ISSUE_CHUNK(5, 2); ISSUE_CHUNK(6, 0); }
        else if (g == 2) { ISSUE_CHUNK(7, 1); }
    }

    // stage accumulators to smem (128 rows x 128 cols, row pad 132 floats)
    {
        float* stage = (float*)smem;
        const int r0 = lane >> 2, cp2 = (lane & 3) * 2;
#pragma unroll
        for (int tm = 0; tm < 2; tm++) {
            int mr = wm * 32 + tm * 16 + r0;
#pragma unroll
            for (int j = 0; j < 8; j++) {
                int nc = wn * 64 + j * 8 + cp2;
                stage[(size_t)mr * 132 + nc]           = acc[tm][j][0];
                stage[(size_t)mr * 132 + nc + 1]       = acc[tm][j][1];
                stage[(size_t)(mr + 8) * 132 + nc]     = acc[tm][j][2];
                stage[(size_t)(mr + 8) * 132 + nc + 1] = acc[tm][j][3];
            }
        }
    }
    __syncthreads();

    // fused LSTM epilogue: each item = (row mloc, 8 consecutive h of 32)
    {
        const float* stage = (const float*)smem;
#pragma unroll 1
        for (int u = 0; u < 2; u++) {
            int item = u * 256 + tid;             // 512 items
            int hu = item & 3, mloc = item >> 2;
            int m = m0 + mloc;
            int t = m >> 6, b = m & 63;
            int hbase = bx * 32 + hu * 8;

            const float4* bp = g_bias4 + (size_t)(l * B_ + b) * H_ + hbase;
            const float* c0p = c0 + ((size_t)l * B_ + b) * H_ + hbase;
            float hv[8], cc[8];
#pragma unroll
            for (int q = 0; q < 8; q++) {
                float4 pre = *(const float4*)&stage[(size_t)mloc * 132 + (hu * 8 + q) * 4];
                float4 bv = bp[q];
                float f  = sigmoidf_(pre.x + bv.x);
                float ii = sigmoidf_(pre.y + bv.y);
                float gt = tanhf_(pre.z + bv.z);
                float o  = sigmoidf_(pre.w + bv.w);
                cc[q] = fmaf(f, c0p[q], ii * gt);
                hv[q] = o * tanhf_(cc[q]);
            }
            size_t ob = (size_t)t * (L_ * B_ * H_) + (size_t)l * (B_ * H_) +
                        (size_t)b * H_ + hbase;
            *(float4*)&hn[ob]     = make_float4(hv[0], hv[1], hv[2], hv[3]);
            *(float4*)&hn[ob + 4] = make_float4(hv[4], hv[5], hv[6], hv[7]);
            *(float4*)&cn[ob]     = make_float4(cc[0], cc[1], cc[2], cc[3]);
            *(float4*)&cn[ob + 4] = make_float4(cc[4], cc[5], cc[6], cc[7]);

            if (write_a) {
                // emit bf16 hi/lo A-image unit for the next layer
                uint32_t hi[4], lo[4];
#pragma unroll
                for (int p = 0; p < 4; p++) {
                    float h0f = __bfloat162float(__float2bfloat16(hv[2 * p]));
                    float h1f = __bfloat162float(__float2bfloat16(hv[2 * p + 1]));
                    hi[p] = pack_bf16x2(hv[2 * p], hv[2 * p + 1]);
                    lo[p] = pack_bf16x2(hv[2 * p] - h0f, hv[2 * p + 1] - h1f);
                }
                int k8 = (hbase >> 3);            // unit index 0..31
                int kb = k8 >> 3, j = k8 & 7;
                size_t base = (size_t)(m >> 7) * 131072 + (size_t)kb * 16384 +
                              (size_t)mloc * 128 +
                              (((unsigned)j ^ ((unsigned)mloc & 7)) << 4);
                *(uint4*)(g_A + base)         = make_uint4(hi[0], hi[1], hi[2], hi[3]);
                *(uint4*)(g_A + base + 65536) = make_uint4(lo[0], lo[1], lo[2], lo[3]);
            } else if (x_out) {
                float* xp = x_out + (size_t)m * H_ + hbase;
                *(float4*)xp       = make_float4(hv[0], hv[1], hv[2], hv[3]);
                *(float4*)(xp + 4) = make_float4(hv[4], hv[5], hv[6], hv[7]);
            }
        }
    }
#undef ISSUE_CHUNK
}

// ---------------------------------------------------------------------------
// Launch. Output layout: [ x (T*B*H) | h_n (T*L*B*H) | c_n (T*L*B*H) ]
// ---------------------------------------------------------------------------
extern "C" void kernel_launch(void* const* d_in, const int* in_sizes, int n_in,
                              void* d_out, int out_size)
{
    const float* inputs = (const float*)d_in[0];   // [T,B,D]
    const float* h0     = (const float*)d_in[1];   // [L,B,H]
    const float* c0     = (const float*)d_in[2];   // [L,B,H]
    const float* W      = (const float*)d_in[3];   // [L,4,D+H,H]
    const float* bb     = (const float*)d_in[4];   // [L,4,H]

    float* out   = (float*)d_out;
    float* x_out = out;
    float* hn    = out + (size_t)T_ * B_ * H_;
    float* cn    = hn + (size_t)T_ * L_ * B_ * H_;

    cudaFuncSetAttribute(gemm_kernel,
                         cudaFuncAttributeMaxDynamicSharedMemorySize, SMEM_SZ);

    wprep_kernel<<<512, 256>>>(W);
    bias_kernel<<<512, 256>>>(h0, W, bb);
    aprep_kernel<<<16384, 256>>>(inputs, B_ * D_);

    dim3 grid(8, M_ / 128);
    // layer 0: epilogue also writes layer-1's A-image (write_a = 1)
    gemm_kernel<<<grid, 256, SMEM_SZ>>>(c0, 0, hn, cn, nullptr, 1);
    // layer 1: writes x
    gemm_kernel<<<grid, 256, SMEM_SZ>>>(c0, 1, hn, cn, x_out, 0);
}